// round 1
// baseline (speedup 1.0000x reference)
#include <cuda_runtime.h>

#define BSZ   128
#define NNODE 4000
#define DF    128
#define NB    10
#define SEQ   400
#define C1    32
#define C2    32
#define MTILE 64
#define MTOT  (BSZ*SEQ)   // 51200 output positions (b,s)

// Scratch (device globals: no allocation allowed in kernel_launch)
__device__ float g_w1t[NB*DF*C1];   // [k][d][c1]
__device__ float g_fcwt[SEQ*C2];    // [s][c2]
__device__ float g_w2t[C1*C2];      // [c1][c2]
__device__ float g_partial[MTOT];   // per-(b,s) FC partial sums

// ---------------------------------------------------------------------------
// Prep: transpose weights into access-friendly layouts (runs every call; cheap)
// ---------------------------------------------------------------------------
__global__ void prep_kernel(const float* __restrict__ w1,
                            const float* __restrict__ fcw,
                            const float* __restrict__ w2) {
    int i = blockIdx.x * blockDim.x + threadIdx.x;
    if (i < NB*DF*C1) {
        int k  = i / (DF*C1);
        int r  = i - k*DF*C1;
        int d  = r / C1;
        int c1 = r - d*C1;
        g_w1t[i] = w1[c1*(DF*NB) + d*NB + k];   // conv1_w [C1][DF][NB]
    }
    if (i < SEQ*C2) {
        int s = i / C2, c2 = i - s*C2;
        g_fcwt[i] = fcw[c2*SEQ + s];            // fc_w [1][C2*SEQ]
    }
    if (i < C1*C2) {
        int c1 = i / C2, c2 = i - c1*C2;
        g_w2t[i] = w2[c2*C1 + c1];              // conv2_w [C2][C1][1]
    }
}

// ---------------------------------------------------------------------------
// Fused gather + conv1 + relu + conv2 + relu + FC-partial
// Grid: MTOT/MTILE = 800 CTAs, 256 threads (8 warps x 8 rows, lane = c1)
// ---------------------------------------------------------------------------
__global__ __launch_bounds__(256, 3) void conv_kernel(
    const int*   __restrict__ recep,
    const float* __restrict__ nf,
    const float* __restrict__ b1,
    const float* __restrict__ b2)
{
    __shared__ float4 sA[MTILE * (DF/4)];   // gathered rows, 64x128 f32 = 32 KB
    __shared__ float  sB[DF * C1];          // weight chunk [d][c1]  = 16 KB

    const int tid  = threadIdx.x;
    const int warp = tid >> 5;
    const int lane = tid & 31;
    const int m0   = blockIdx.x * MTILE;

    float4 acc[8];
#pragma unroll
    for (int r = 0; r < 8; r++) acc[r] = make_float4(0.f, 0.f, 0.f, 0.f);

    for (int k = 0; k < NB; k++) {
        // --- load weight chunk k: contiguous 16 KB, coalesced float4
        {
            const float4* bs = (const float4*)(g_w1t + k*DF*C1);
            float4* bd = (float4*)sB;
#pragma unroll
            for (int i = 0; i < 4; i++) bd[tid + i*256] = bs[tid + i*256];
        }
        // --- gather 64 node rows (each 512B contiguous, coalesced per row)
#pragma unroll
        for (int j = 0; j < 8; j++) {
            int slot = tid + j*256;
            int row  = slot >> 5;       // 0..63
            int dq   = slot & 31;       // float4 index within row
            int m    = m0 + row;
            int b    = m / SEQ;
            int s    = m - b*SEQ;
            int node = recep[b*NNODE + s*NB + k] + b*NNODE;
            sA[row*32 + dq] = ((const float4*)(nf + (size_t)node * DF))[dq];
        }
        __syncthreads();

        // --- compute: per warp 8 rows x 32 cols x 128 K
        const float4* aw = sA + (warp*8)*32;
#pragma unroll 8
        for (int dq = 0; dq < 32; dq++) {
            float b0 = sB[(dq*4 + 0)*C1 + lane];   // conflict-free (consecutive)
            float bb = sB[(dq*4 + 1)*C1 + lane];
            float bc = sB[(dq*4 + 2)*C1 + lane];
            float bd = sB[(dq*4 + 3)*C1 + lane];
#pragma unroll
            for (int r = 0; r < 8; r++) {
                float4 a = aw[r*32 + dq];          // broadcast within warp
                acc[r].x = fmaf(a.x, b0, acc[r].x);
                acc[r].y = fmaf(a.y, bb, acc[r].y);
                acc[r].z = fmaf(a.z, bc, acc[r].z);
                acc[r].w = fmaf(a.w, bd, acc[r].w);
            }
        }
        __syncthreads();
    }

    // --- conv1 bias + relu
    float bias1 = b1[lane];
    float y1[8];
#pragma unroll
    for (int r = 0; r < 8; r++) {
        float v = (acc[r].x + acc[r].y) + (acc[r].z + acc[r].w) + bias1;
        y1[r] = fmaxf(v, 0.f);
    }

    // --- stash y1 to smem (reuse sA region), load w2t into sB front
    float* y1s = (float*)sA;                       // [64][32]
#pragma unroll
    for (int r = 0; r < 8; r++) y1s[(warp*8 + r)*32 + lane] = y1[r];
    ((float4*)sB)[tid] = ((const float4*)g_w2t)[tid];   // 1024 floats
    __syncthreads();

    // --- conv2 (1x1) + relu + FC partial
    float bias2 = b2[lane];
#pragma unroll
    for (int r = 0; r < 8; r++) {
        int m = m0 + warp*8 + r;
        int b = m / SEQ;
        int s = m - b*SEQ;
        float v = bias2;
#pragma unroll
        for (int c1 = 0; c1 < C1; c1++)
            v = fmaf(sB[c1*C2 + lane], y1s[(warp*8 + r)*32 + c1], v);
        v = fmaxf(v, 0.f);
        float p = v * g_fcwt[s*C2 + lane];         // coalesced
#pragma unroll
        for (int off = 16; off > 0; off >>= 1)
            p += __shfl_xor_sync(0xffffffffu, p, off);
        if (lane == 0) g_partial[m] = p;
    }
}

// ---------------------------------------------------------------------------
// Final reduce: 400 partials -> 1 per graph, + fc bias
// ---------------------------------------------------------------------------
__global__ void reduce_kernel(const float* __restrict__ fcb,
                              float* __restrict__ out) {
    __shared__ float red[128];
    int b = blockIdx.x, tid = threadIdx.x;
    float s = 0.f;
    for (int i = tid; i < SEQ; i += 128) s += g_partial[b*SEQ + i];
    red[tid] = s;
    __syncthreads();
    for (int st = 64; st > 0; st >>= 1) {
        if (tid < st) red[tid] += red[tid + st];
        __syncthreads();
    }
    if (tid == 0) out[b] = red[0] + fcb[0];
}

// ---------------------------------------------------------------------------
extern "C" void kernel_launch(void* const* d_in, const int* in_sizes, int n_in,
                              void* d_out, int out_size) {
    const int*   recep = (const int*)  d_in[0];
    const float* nf    = (const float*)d_in[1];
    const float* w1    = (const float*)d_in[2];
    const float* b1    = (const float*)d_in[3];
    const float* w2    = (const float*)d_in[4];
    const float* b2    = (const float*)d_in[5];
    const float* fcw   = (const float*)d_in[6];
    const float* fcb   = (const float*)d_in[7];
    float* out = (float*)d_out;

    prep_kernel<<<(NB*DF*C1 + 255)/256, 256>>>(w1, fcw, w2);
    conv_kernel<<<MTOT/MTILE, 256>>>(recep, nf, b1, b2);
    reduce_kernel<<<BSZ, 128>>>(fcb, out);
}

// round 4
// speedup vs baseline: 1.1744x; 1.1744x over previous
#include <cuda_runtime.h>
#include <cstdint>

#define BSZ   128
#define NNODE 4000
#define DF    128
#define NB    10
#define SEQ   400
#define C1    32
#define C2    32
#define MTILE 128
#define MTOT  (BSZ*SEQ)          // 51200
#define NCTA  (MTOT/MTILE)       // 400

#define A_STRIDE 132             // floats per gathered row (pad: conflict-free LDS)
#define B_STRIDE 36              // floats per weight d-row (pad: conflict-free LDS)
#define SM_A     (MTILE*NB)                  // sIdx occupies [0, 1280) ints
#define SM_B     (SM_A + MTILE*A_STRIDE)     // 1280 + 16896 = 18176
#define SM_FLOATS (SM_B + DF*B_STRIDE)       // 18176 + 4608 = 22784
#define SM_BYTES  (SM_FLOATS*4)              // 91136 B -> 2 CTAs/SM

__device__ float g_w1t[NB*DF*C1];   // [k][d][c1], tf32-rounded
__device__ float g_partial[MTOT];

__device__ __forceinline__ float to_tf32(float x) {
    float r; asm("cvt.rna.tf32.f32 %0, %1;" : "=f"(r) : "f"(x)); return r;
}

__device__ __forceinline__ void mma1688(float* c, const uint32_t* a,
                                        uint32_t b0, uint32_t b1) {
    asm volatile(
        "mma.sync.aligned.m16n8k8.row.col.f32.tf32.tf32.f32 "
        "{%0,%1,%2,%3}, {%4,%5,%6,%7}, {%8,%9}, {%0,%1,%2,%3};"
        : "+f"(c[0]), "+f"(c[1]), "+f"(c[2]), "+f"(c[3])
        : "r"(a[0]), "r"(a[1]), "r"(a[2]), "r"(a[3]), "r"(b0), "r"(b1));
}

// ---------------------------------------------------------------------------
// prep: conv1 weights -> [k][d][c1] with tf32 rounding
// ---------------------------------------------------------------------------
__global__ void prep_kernel(const float* __restrict__ w1) {
    int i = blockIdx.x * blockDim.x + threadIdx.x;     // 40960
    if (i >= NB * DF * C1) return;
    int k   = i / (DF * C1);
    int rem = i - k * (DF * C1);
    int d   = rem >> 5;
    int c1  = rem & 31;
    g_w1t[i] = to_tf32(w1[c1 * (DF * NB) + d * NB + k]);
}

// ---------------------------------------------------------------------------
// fused gather + tf32 mma.sync conv1 + relu + conv2 + relu + FC partial
// ---------------------------------------------------------------------------
__global__ __launch_bounds__(256, 2) void conv_kernel(
    const int*   __restrict__ recep,
    const float* __restrict__ nf,
    const float* __restrict__ b1,
    const float* __restrict__ w2,
    const float* __restrict__ b2,
    const float* __restrict__ fcw)
{
    extern __shared__ float sm[];
    int*   sIdx = (int*)sm;
    float* sA   = sm + SM_A;
    float* sB   = sm + SM_B;

    const int tid  = threadIdx.x;
    const int wid  = tid >> 5;
    const int lane = tid & 31;
    const int m0   = blockIdx.x * MTILE;
    const int fr   = lane >> 2;      // fragment row 0..7
    const int fc   = lane & 3;       // fragment col 0..3

    // node indices for all (row, k): contiguous-ish recep reads
    for (int i = tid; i < MTILE * NB; i += 256) {
        int row = i / NB;
        int k   = i - row * NB;
        int m   = m0 + row;
        int b   = m / SEQ;
        int s   = m - b * SEQ;
        sIdx[i] = recep[b * NNODE + s * NB + k] + b * NNODE;
    }

    float acc[4][4];
#pragma unroll
    for (int nt = 0; nt < 4; nt++)
#pragma unroll
        for (int j = 0; j < 4; j++) acc[nt][j] = 0.f;

    for (int k = 0; k < NB; k++) {
        __syncthreads();   // sIdx ready (k=0) / sA no longer read (k>0)

        // gather: one 512B row per warp-instruction, tf32-round, padded STS
#pragma unroll
        for (int j = 0; j < 16; j++) {
            int slot = tid + j * 256;          // 0..4095
            int row  = slot >> 5;
            int q    = slot & 31;
            int node = sIdx[row * NB + k];     // LDS broadcast
            float4 v = ((const float4*)(nf + (size_t)node * DF))[q];
            v.x = to_tf32(v.x); v.y = to_tf32(v.y);
            v.z = to_tf32(v.z); v.w = to_tf32(v.w);
            *(float4*)(sA + row * A_STRIDE + q * 4) = v;
        }
        // weight chunk: 16KB contiguous (L2-hot), padded rows
#pragma unroll
        for (int j = 0; j < 4; j++) {
            int i4 = tid + j * 256;            // 0..1023 float4s
            int d  = i4 >> 3;
            int c4 = i4 & 7;
            float4 v = ((const float4*)(g_w1t + k * 4096))[i4];
            *(float4*)(sB + d * B_STRIDE + c4 * 4) = v;
        }
        __syncthreads();

        // compute: warp owns rows [wid*16, wid*16+16), all 32 cols, K=128
        const float* aw = sA + (wid * 16) * A_STRIDE;
#pragma unroll
        for (int t = 0; t < 16; t++) {
            const int k0 = t * 8;
            uint32_t a[4];
            a[0] = __float_as_uint(aw[fr       * A_STRIDE + k0 + fc]);
            a[1] = __float_as_uint(aw[(fr + 8) * A_STRIDE + k0 + fc]);
            a[2] = __float_as_uint(aw[fr       * A_STRIDE + k0 + 4 + fc]);
            a[3] = __float_as_uint(aw[(fr + 8) * A_STRIDE + k0 + 4 + fc]);
#pragma unroll
            for (int nt = 0; nt < 4; nt++) {
                uint32_t b0 = __float_as_uint(sB[(k0 + fc)     * B_STRIDE + nt * 8 + fr]);
                uint32_t b1v= __float_as_uint(sB[(k0 + 4 + fc) * B_STRIDE + nt * 8 + fr]);
                mma1688(acc[nt], a, b0, b1v);
            }
        }
    }
    __syncthreads();   // all mma reads of sA done

    // y1 = relu(conv1 + b1) -> smem [128][33]; w2 -> smem
    float* y1s = sA;                    // stride 33, 4224 floats
    const int rb = wid * 16;
#pragma unroll
    for (int nt = 0; nt < 4; nt++) {
        int col = nt * 8 + 2 * fc;
        float bc0 = __ldg(b1 + col), bc1 = __ldg(b1 + col + 1);
        y1s[(rb + fr)     * 33 + col]     = fmaxf(acc[nt][0] + bc0, 0.f);
        y1s[(rb + fr)     * 33 + col + 1] = fmaxf(acc[nt][1] + bc1, 0.f);
        y1s[(rb + fr + 8) * 33 + col]     = fmaxf(acc[nt][2] + bc0, 0.f);
        y1s[(rb + fr + 8) * 33 + col + 1] = fmaxf(acc[nt][3] + bc1, 0.f);
    }
    float* w2s = sB;                    // 1024 floats [c2][c1]
    ((float4*)w2s)[tid] = ((const float4*)w2)[tid & 255];
    __syncthreads();

    // conv2 (fp32) + relu + FC partial: thread <-> row
    if (tid < MTILE) {
        int m = m0 + tid;
        int b = m / SEQ;
        int s = m - b * SEQ;
        const float* yr = y1s + tid * 33;
        float p = 0.f;
#pragma unroll
        for (int c2 = 0; c2 < C2; c2++) {
            float v = __ldg(b2 + c2);
            const float* wv = w2s + c2 * 32;
#pragma unroll
            for (int q = 0; q < 32; q += 4) {
                v = fmaf(wv[q],     yr[q],     v);
                v = fmaf(wv[q + 1], yr[q + 1], v);
                v = fmaf(wv[q + 2], yr[q + 2], v);
                v = fmaf(wv[q + 3], yr[q + 3], v);
            }
            v = fmaxf(v, 0.f);
            p = fmaf(v, __ldg(fcw + c2 * SEQ + s), p);   // coalesced over threads
        }
        g_partial[m] = p;
    }
}

// ---------------------------------------------------------------------------
__global__ void reduce_kernel(const float* __restrict__ fcb, float* __restrict__ out) {
    __shared__ float red[128];
    int b = blockIdx.x, tid = threadIdx.x;
    float s = 0.f;
    for (int i = tid; i < SEQ; i += 128) s += g_partial[b * SEQ + i];
    red[tid] = s;
    __syncthreads();
    for (int st = 64; st > 0; st >>= 1) {
        if (tid < st) red[tid] += red[tid + st];
        __syncthreads();
    }
    if (tid == 0) out[b] = red[0] + fcb[0];
}

// ---------------------------------------------------------------------------
extern "C" void kernel_launch(void* const* d_in, const int* in_sizes, int n_in,
                              void* d_out, int out_size) {
    const int*   recep = (const int*)  d_in[0];
    const float* nf    = (const float*)d_in[1];
    const float* w1    = (const float*)d_in[2];
    const float* b1    = (const float*)d_in[3];
    const float* w2    = (const float*)d_in[4];
    const float* b2    = (const float*)d_in[5];
    const float* fcw   = (const float*)d_in[6];
    const float* fcb   = (const float*)d_in[7];
    float* out = (float*)d_out;

    cudaFuncSetAttribute(conv_kernel, cudaFuncAttributeMaxDynamicSharedMemorySize, SM_BYTES);
    prep_kernel<<<(NB*DF*C1 + 255) / 256, 256>>>(w1);
    conv_kernel<<<NCTA, 256, SM_BYTES>>>(recep, nf, b1, w2, b2, fcw);
    reduce_kernel<<<BSZ, 128>>>(fcb, out);
}

// round 5
// speedup vs baseline: 2.7417x; 2.3345x over previous
#include <cuda_runtime.h>
#include <cstdint>

#define BSZ   128
#define NNODE 4000
#define DF    128
#define NB    10
#define SEQ   400
#define C1    32
#define C2    32
#define MTILE 128
#define MTOT  (BSZ*SEQ)          // 51200
#define NCTA  (MTOT/MTILE)       // 400

// ---- shared memory byte layout --------------------------------------------
#define SMB_IDX   0                         // 1280 ints = 5120 B
#define SMB_A     5120                      // 2 stages x 64 KB (dense, swizzled)
#define A_STAGE   (MTILE*DF*4)              // 65536
#define SMB_B     (SMB_A + 2*A_STAGE)       // 136192
#define B_STAGE   (DF*144)                  // 18432 (144B padded rows)
#define SMB_TOTAL (SMB_B + 2*B_STAGE)       // 173056

__device__ float g_w1t[NB*DF*C1];   // [k][d][c1], tf32-rounded (rna)
__device__ float g_partial[MTOT];

__device__ __forceinline__ float to_tf32(float x) {
    float r; asm("cvt.rna.tf32.f32 %0, %1;" : "=f"(r) : "f"(x)); return r;
}
__device__ __forceinline__ uint32_t smem_u32(const void* p) {
    uint32_t a;
    asm("{ .reg .u64 t; cvta.to.shared.u64 t, %1; cvt.u32.u64 %0, t; }" : "=r"(a) : "l"(p));
    return a;
}
__device__ __forceinline__ void cp16(uint32_t dst, const void* src) {
    asm volatile("cp.async.cg.shared.global [%0], [%1], 16;" :: "r"(dst), "l"(src));
}
#define CP_COMMIT() asm volatile("cp.async.commit_group;" ::: "memory")
#define CP_WAIT(N)  asm volatile("cp.async.wait_group %0;" :: "n"(N) : "memory")

__device__ __forceinline__ void mma1688(float* c, const uint32_t* a,
                                        uint32_t b0, uint32_t b1) {
    asm volatile(
        "mma.sync.aligned.m16n8k8.row.col.f32.tf32.tf32.f32 "
        "{%0,%1,%2,%3}, {%4,%5,%6,%7}, {%8,%9}, {%0,%1,%2,%3};"
        : "+f"(c[0]), "+f"(c[1]), "+f"(c[2]), "+f"(c[3])
        : "r"(a[0]), "r"(a[1]), "r"(a[2]), "r"(a[3]), "r"(b0), "r"(b1));
}

// ---------------------------------------------------------------------------
// prep: conv1 weights -> [k][d][c1], tf32-rounded
// ---------------------------------------------------------------------------
__global__ void prep_kernel(const float* __restrict__ w1) {
    int i = blockIdx.x * blockDim.x + threadIdx.x;     // 40960
    if (i >= NB * DF * C1) return;
    int k   = i / (DF * C1);
    int rem = i - k * (DF * C1);
    int d   = rem >> 5;
    int c1  = rem & 31;
    g_w1t[i] = to_tf32(w1[c1 * (DF * NB) + d * NB + k]);
}

// ---------------------------------------------------------------------------
// fused: cp.async-pipelined gather + tf32 mma conv1 + relu + conv2 + relu + FC
// ---------------------------------------------------------------------------
__global__ __launch_bounds__(256, 1) void conv_kernel(
    const int*   __restrict__ recep,
    const float* __restrict__ nf,
    const float* __restrict__ b1,
    const float* __restrict__ w2,
    const float* __restrict__ b2,
    const float* __restrict__ fcw)
{
    extern __shared__ char smem[];
    const uint32_t sbase = smem_u32(smem);
    int*   sIdx = (int*)(smem + SMB_IDX);
    const int tid  = threadIdx.x;
    const int wid  = tid >> 5;
    const int lane = tid & 31;
    const int m0   = blockIdx.x * MTILE;
    const int fr   = lane >> 2;      // fragment row 0..7
    const int fc   = lane & 3;       // fragment col 0..3

    // node indices for all (row, k)
    for (int i = tid; i < MTILE * NB; i += 256) {
        int row = i / NB;
        int k   = i - row * NB;
        int m   = m0 + row;
        int b   = m / SEQ;
        int s   = m - b * SEQ;
        sIdx[i] = recep[b * NNODE + s * NB + k] + b * NNODE;
    }
    __syncthreads();

    // prefetch issue: A rows (swizzled float4) + B chunk (padded rows)
    auto prefetch = [&](int k, int st) {
        uint32_t abase = sbase + SMB_A + st * A_STAGE;
#pragma unroll
        for (int j = 0; j < 16; j++) {
            int row = wid + j * 8;                 // slot = tid + j*256
            int q   = lane;
            int node = sIdx[row * NB + k];         // broadcast LDS
            cp16(abase + (uint32_t)row * 512u + (uint32_t)((q ^ (row & 7)) * 16),
                 nf + (size_t)node * DF + q * 4);
        }
        uint32_t bbase = sbase + SMB_B + st * B_STAGE;
        const float4* bsrc = (const float4*)(g_w1t + k * 4096);
#pragma unroll
        for (int j = 0; j < 4; j++) {
            int i4 = tid + j * 256;                // 0..1023
            int d  = i4 >> 3;
            int c4 = i4 & 7;
            cp16(bbase + (uint32_t)d * 144u + (uint32_t)c4 * 16u, bsrc + i4);
        }
        CP_COMMIT();
    };

    prefetch(0, 0);
    prefetch(1, 1);

    float acc[4][4];
#pragma unroll
    for (int nt = 0; nt < 4; nt++)
#pragma unroll
        for (int j = 0; j < 4; j++) acc[nt][j] = 0.f;

    for (int k = 0; k < NB; k++) {
        const int st = k & 1;
        if (k < NB - 1) CP_WAIT(1); else CP_WAIT(0);
        __syncthreads();                            // stage st of A/B visible to all

        const float* aw = (const float*)(smem + SMB_A + st * A_STAGE) + (wid * 16) * DF;
        const float* bw = (const float*)(smem + SMB_B + st * B_STAGE);
#pragma unroll
        for (int t = 0; t < 16; t++) {
            // A fragment: rows fr / fr+8, cols 8t+fc, 8t+4+fc (swizzled float4 layout)
            const int q0 = (2 * t) ^ fr;            // float4 index of col 8t..8t+3
            const int q1 = (2 * t + 1) ^ fr;        // float4 index of col 8t+4..
            uint32_t a[4];
            a[0] = __float_as_uint(to_tf32(aw[fr       * DF + q0 * 4 + fc]));
            a[1] = __float_as_uint(to_tf32(aw[(fr + 8) * DF + q0 * 4 + fc]));
            a[2] = __float_as_uint(to_tf32(aw[fr       * DF + q1 * 4 + fc]));
            a[3] = __float_as_uint(to_tf32(aw[(fr + 8) * DF + q1 * 4 + fc]));
#pragma unroll
            for (int nt = 0; nt < 4; nt++) {
                uint32_t b0 = __float_as_uint(bw[(8 * t + fc)     * 36 + nt * 8 + fr]);
                uint32_t b1v= __float_as_uint(bw[(8 * t + 4 + fc) * 36 + nt * 8 + fr]);
                mma1688(acc[nt], a, b0, b1v);
            }
        }
        __syncthreads();                            // done reading stage st
        if (k + 2 < NB) prefetch(k + 2, st);        // refill the stage just freed
    }

    // y1 = relu(conv1 + b1) -> smem [128][33]; w2 -> smem
    float* y1s = (float*)(smem + SMB_A);            // 16.9 KB, stage area free now
    float* w2s = (float*)(smem + SMB_B);            // 4 KB
    const int rb = wid * 16;
#pragma unroll
    for (int nt = 0; nt < 4; nt++) {
        int col = nt * 8 + 2 * fc;
        float bc0 = __ldg(b1 + col), bc1 = __ldg(b1 + col + 1);
        y1s[(rb + fr)     * 33 + col]     = fmaxf(acc[nt][0] + bc0, 0.f);
        y1s[(rb + fr)     * 33 + col + 1] = fmaxf(acc[nt][1] + bc1, 0.f);
        y1s[(rb + fr + 8) * 33 + col]     = fmaxf(acc[nt][2] + bc0, 0.f);
        y1s[(rb + fr + 8) * 33 + col + 1] = fmaxf(acc[nt][3] + bc1, 0.f);
    }
    if (tid < 256) ((float4*)w2s)[tid] = ((const float4*)w2)[tid & 255];
    __syncthreads();

    // conv2 (fp32) + relu + FC partial: one thread per output row
    if (tid < MTILE) {
        int m = m0 + tid;
        int b = m / SEQ;
        int s = m - b * SEQ;
        const float* yr = y1s + tid * 33;
        float p = 0.f;
#pragma unroll
        for (int c2 = 0; c2 < C2; c2++) {
            float v = __ldg(b2 + c2);
            const float* wv = w2s + c2 * 32;
#pragma unroll
            for (int q = 0; q < 32; q += 4) {
                v = fmaf(wv[q],     yr[q],     v);
                v = fmaf(wv[q + 1], yr[q + 1], v);
                v = fmaf(wv[q + 2], yr[q + 2], v);
                v = fmaf(wv[q + 3], yr[q + 3], v);
            }
            v = fmaxf(v, 0.f);
            p = fmaf(v, __ldg(fcw + c2 * SEQ + s), p);
        }
        g_partial[m] = p;
    }
}

// ---------------------------------------------------------------------------
__global__ void reduce_kernel(const float* __restrict__ fcb, float* __restrict__ out) {
    __shared__ float red[128];
    int b = blockIdx.x, tid = threadIdx.x;
    float s = 0.f;
    for (int i = tid; i < SEQ; i += 128) s += g_partial[b * SEQ + i];
    red[tid] = s;
    __syncthreads();
    for (int st = 64; st > 0; st >>= 1) {
        if (tid < st) red[tid] += red[tid + st];
        __syncthreads();
    }
    if (tid == 0) out[b] = red[0] + fcb[0];
}

// ---------------------------------------------------------------------------
extern "C" void kernel_launch(void* const* d_in, const int* in_sizes, int n_in,
                              void* d_out, int out_size) {
    const int*   recep = (const int*)  d_in[0];
    const float* nf    = (const float*)d_in[1];
    const float* w1    = (const float*)d_in[2];
    const float* b1    = (const float*)d_in[3];
    const float* w2    = (const float*)d_in[4];
    const float* b2    = (const float*)d_in[5];
    const float* fcw   = (const float*)d_in[6];
    const float* fcb   = (const float*)d_in[7];
    float* out = (float*)d_out;

    cudaFuncSetAttribute(conv_kernel, cudaFuncAttributeMaxDynamicSharedMemorySize, SMB_TOTAL);
    prep_kernel<<<(NB*DF*C1 + 255) / 256, 256>>>(w1);
    conv_kernel<<<NCTA, 256, SMB_TOTAL>>>(recep, nf, b1, w2, b2, fcw);
    reduce_kernel<<<BSZ, 128>>>(fcb, out);
}

// round 6
// speedup vs baseline: 4.3083x; 1.5714x over previous
#include <cuda_runtime.h>
#include <cuda_fp16.h>
#include <cstdint>

#define BSZ   128
#define NNODE 4000
#define DF    128
#define NB    10
#define SEQ   400
#define C1    32
#define C2    32
#define MTILE 128
#define MTOT  (BSZ*SEQ)          // 51200
#define NCTA  (MTOT/MTILE)       // 400
#define NSTAGE 20                // NB * 2 half-K stages

// ---- shared memory byte layout --------------------------------------------
#define SMB_IDX   0                         // 1280 ints = 5120 B
#define SMB_A     5120                      // 2 x 32 KB fp32 half-K stages
#define A_STAGE   (MTILE*64*4)              // 32768
#define SMB_B     (SMB_A + 2*A_STAGE)       // 70656
#define B_STAGE   (32*160)                  // 5120 (32 pair-rows x 160B padded)
#define SMB_TOTAL (SMB_B + 2*B_STAGE)       // 80896  -> 2 CTAs/SM

__device__ uint32_t g_w1h[NB*64*40];  // f16 pairs: [k][pair(d/2)][c1], 40-u32 rows
__device__ float    g_partial[MTOT];

__device__ __forceinline__ uint32_t smem_u32(const void* p) {
    uint32_t a;
    asm("{ .reg .u64 t; cvta.to.shared.u64 t, %1; cvt.u32.u64 %0, t; }" : "=r"(a) : "l"(p));
    return a;
}
__device__ __forceinline__ void cp16(uint32_t dst, const void* src) {
    asm volatile("cp.async.cg.shared.global [%0], [%1], 16;" :: "r"(dst), "l"(src));
}
#define CP_COMMIT() asm volatile("cp.async.commit_group;" ::: "memory")
#define CP_WAIT(N)  asm volatile("cp.async.wait_group %0;" :: "n"(N) : "memory")

// pack float2 -> f16x2 (lo = first element)
__device__ __forceinline__ uint32_t packh2(float2 v) {
    uint32_t r;
    asm("cvt.rn.f16x2.f32 %0, %1, %2;" : "=r"(r) : "f"(v.y), "f"(v.x));
    return r;
}
__device__ __forceinline__ void mma16816(float* c, uint32_t a0, uint32_t a1,
                                         uint32_t a2, uint32_t a3,
                                         uint32_t b0, uint32_t b1) {
    asm volatile(
        "mma.sync.aligned.m16n8k16.row.col.f32.f16.f16.f32 "
        "{%0,%1,%2,%3}, {%4,%5,%6,%7}, {%8,%9}, {%0,%1,%2,%3};"
        : "+f"(c[0]), "+f"(c[1]), "+f"(c[2]), "+f"(c[3])
        : "r"(a0), "r"(a1), "r"(a2), "r"(a3), "r"(b0), "r"(b1));
}

// ---------------------------------------------------------------------------
// prep: conv1 weights -> f16 pair-interleaved [k][d/2][c1] rows (40 u32 pad)
// ---------------------------------------------------------------------------
__global__ void prep_kernel(const float* __restrict__ w1) {
    int i = blockIdx.x * blockDim.x + threadIdx.x;     // 40960
    if (i >= NB * DF * C1) return;
    int k   = i >> 12;
    int rem = i & 4095;
    int d   = rem >> 5;
    int c1  = rem & 31;
    float v = w1[c1 * (DF * NB) + d * NB + k];
    ((__half*)g_w1h)[((size_t)k * 2560 + (d >> 1) * 40 + c1) * 2 + (d & 1)] =
        __float2half_rn(v);
}

// ---------------------------------------------------------------------------
// fused: cp.async pipeline + f16 m16n8k16 conv1 + relu + conv2 + relu + FC
// ---------------------------------------------------------------------------
__global__ __launch_bounds__(256, 2) void conv_kernel(
    const int*   __restrict__ recep,
    const float* __restrict__ nf,
    const float* __restrict__ b1,
    const float* __restrict__ w2,
    const float* __restrict__ b2,
    const float* __restrict__ fcw)
{
    extern __shared__ char smem[];
    const uint32_t sbase = smem_u32(smem);
    int*   sIdx = (int*)(smem + SMB_IDX);
    const int tid  = threadIdx.x;
    const int wid  = tid >> 5;
    const int lane = tid & 31;
    const int m0   = blockIdx.x * MTILE;
    const int fr   = lane >> 2;      // 0..7
    const int fc   = lane & 3;       // 0..3

    for (int i = tid; i < MTILE * NB; i += 256) {
        int row = i / NB;
        int k   = i - row * NB;
        int m   = m0 + row;
        int b   = m / SEQ;
        int s   = m - b * SEQ;
        sIdx[i] = recep[b * NNODE + s * NB + k] + b * NNODE;
    }
    __syncthreads();

    // stage s: k = s>>1, half h = s&1 (64 K-columns), buffer bi = s&1
    auto prefetch = [&](int s) {
        const int k = s >> 1, h = s & 1, bi = s & 1;
        uint32_t abase = sbase + SMB_A + bi * A_STAGE;
#pragma unroll
        for (int j = 0; j < 8; j++) {
            int slot = tid + j * 256;              // 0..2047
            int row  = slot >> 4;
            int q    = slot & 15;
            int node = sIdx[row * NB + k];
            cp16(abase + (uint32_t)row * 256u +
                     (uint32_t)((q ^ ((row & 7) << 1)) * 16),
                 nf + (size_t)node * DF + h * 64 + q * 4);
        }
        uint32_t bbase = sbase + SMB_B + bi * B_STAGE;
        const char* bsrc = (const char*)g_w1h + (size_t)k * 10240 + h * 32 * 160;
#pragma unroll
        for (int j = 0; j < 2; j++) {
            int slot = tid + j * 256;              // 0..319
            if (slot < 320) {
                int row = slot / 10;
                int c   = slot - row * 10;
                cp16(bbase + (uint32_t)row * 160u + (uint32_t)c * 16u,
                     bsrc + row * 160 + c * 16);
            }
        }
        CP_COMMIT();
    };

    prefetch(0);
    prefetch(1);

    float acc[4][4];
#pragma unroll
    for (int nt = 0; nt < 4; nt++)
#pragma unroll
        for (int j = 0; j < 4; j++) acc[nt][j] = 0.f;

    const int row0 = wid * 16 + fr;
    const int sw   = fr << 1;

    for (int s = 0; s < NSTAGE; s++) {
        const int bi = s & 1;
        if (s < NSTAGE - 1) CP_WAIT(1); else CP_WAIT(0);
        __syncthreads();

        const float*    aw = (const float*)(smem + SMB_A + bi * A_STAGE);
        const uint32_t* bw = (const uint32_t*)(smem + SMB_B + bi * B_STAGE);
#pragma unroll
        for (int t = 0; t < 4; t++) {
            const int q0 = (4 * t + (fc >> 1)) ^ sw;       // cols 16t+2fc
            const int q1 = (4 * t + 2 + (fc >> 1)) ^ sw;   // cols 16t+8+2fc
            const int oi = (fc & 1) * 2;
            float2 v00 = *(const float2*)(aw + row0 * 64       + q0 * 4 + oi);
            float2 v10 = *(const float2*)(aw + (row0 + 8) * 64 + q0 * 4 + oi);
            float2 v01 = *(const float2*)(aw + row0 * 64       + q1 * 4 + oi);
            float2 v11 = *(const float2*)(aw + (row0 + 8) * 64 + q1 * 4 + oi);
            uint32_t a0 = packh2(v00), a1 = packh2(v10);
            uint32_t a2 = packh2(v01), a3 = packh2(v11);
            const int p0 = (8 * t + fc) * 40;          // k = 16t+2fc,+1
            const int p1 = (8 * t + 4 + fc) * 40;      // k = 16t+8+2fc,+1
#pragma unroll
            for (int nt = 0; nt < 4; nt++) {
                uint32_t b0 = bw[p0 + nt * 8 + fr];
                uint32_t b1v = bw[p1 + nt * 8 + fr];
                mma16816(acc[nt], a0, a1, a2, a3, b0, b1v);
            }
        }
        __syncthreads();
        if (s + 2 < NSTAGE) prefetch(s + 2);
    }

    // y1 = relu(conv1 + b1) -> smem [128][33]; w2 -> smem
    float* y1s = (float*)(smem + SMB_A);
    float* w2s = (float*)(smem + SMB_B);
    const int rb = wid * 16;
#pragma unroll
    for (int nt = 0; nt < 4; nt++) {
        int col = nt * 8 + 2 * fc;
        float bc0 = __ldg(b1 + col), bc1 = __ldg(b1 + col + 1);
        y1s[(rb + fr)     * 33 + col]     = fmaxf(acc[nt][0] + bc0, 0.f);
        y1s[(rb + fr)     * 33 + col + 1] = fmaxf(acc[nt][1] + bc1, 0.f);
        y1s[(rb + fr + 8) * 33 + col]     = fmaxf(acc[nt][2] + bc0, 0.f);
        y1s[(rb + fr + 8) * 33 + col + 1] = fmaxf(acc[nt][3] + bc1, 0.f);
    }
    ((float4*)w2s)[tid & 255] = ((const float4*)w2)[tid & 255];
    __syncthreads();

    // conv2 (fp32) + relu + FC partial: one thread per row
    if (tid < MTILE) {
        int m = m0 + tid;
        int b = m / SEQ;
        int s = m - b * SEQ;
        const float* yr = y1s + tid * 33;
        float p = 0.f;
#pragma unroll
        for (int c2 = 0; c2 < C2; c2++) {
            float v = __ldg(b2 + c2);
            const float* wv = w2s + c2 * 32;
#pragma unroll
            for (int q = 0; q < 32; q += 4) {
                v = fmaf(wv[q],     yr[q],     v);
                v = fmaf(wv[q + 1], yr[q + 1], v);
                v = fmaf(wv[q + 2], yr[q + 2], v);
                v = fmaf(wv[q + 3], yr[q + 3], v);
            }
            v = fmaxf(v, 0.f);
            p = fmaf(v, __ldg(fcw + c2 * SEQ + s), p);
        }
        g_partial[m] = p;
    }
}

// ---------------------------------------------------------------------------
__global__ void reduce_kernel(const float* __restrict__ fcb, float* __restrict__ out) {
    __shared__ float red[128];
    int b = blockIdx.x, tid = threadIdx.x;
    float s = 0.f;
    for (int i = tid; i < SEQ; i += 128) s += g_partial[b * SEQ + i];
    red[tid] = s;
    __syncthreads();
    for (int st = 64; st > 0; st >>= 1) {
        if (tid < st) red[tid] += red[tid + st];
        __syncthreads();
    }
    if (tid == 0) out[b] = red[0] + fcb[0];
}

// ---------------------------------------------------------------------------
extern "C" void kernel_launch(void* const* d_in, const int* in_sizes, int n_in,
                              void* d_out, int out_size) {
    const int*   recep = (const int*)  d_in[0];
    const float* nf    = (const float*)d_in[1];
    const float* w1    = (const float*)d_in[2];
    const float* b1    = (const float*)d_in[3];
    const float* w2    = (const float*)d_in[4];
    const float* b2    = (const float*)d_in[5];
    const float* fcw   = (const float*)d_in[6];
    const float* fcb   = (const float*)d_in[7];
    float* out = (float*)d_out;

    cudaFuncSetAttribute(conv_kernel, cudaFuncAttributeMaxDynamicSharedMemorySize, SMB_TOTAL);
    prep_kernel<<<(NB*DF*C1 + 255) / 256, 256>>>(w1);
    conv_kernel<<<NCTA, 256, SMB_TOTAL>>>(recep, nf, b1, w2, b2, fcw);
    reduce_kernel<<<BSZ, 128>>>(fcb, out);
}